// round 8
// baseline (speedup 1.0000x reference)
#include <cuda_runtime.h>
#include <cuda_fp16.h>

// ---------------------------------------------------------------------------
// f16-accumulate MMA + movmatrix wrappers (sm_75+/sm_80, fine on compute_103)
// ---------------------------------------------------------------------------
__device__ __forceinline__ void mmaf16_16816(unsigned* d, const unsigned* a,
                                             unsigned b0, unsigned b1,
                                             unsigned c0, unsigned c1) {
    asm volatile(
        "mma.sync.aligned.m16n8k16.row.col.f16.f16.f16.f16 "
        "{%0,%1}, {%2,%3,%4,%5}, {%6,%7}, {%8,%9};"
        : "=r"(d[0]), "=r"(d[1])
        : "r"(a[0]), "r"(a[1]), "r"(a[2]), "r"(a[3]),
          "r"(b0), "r"(b1), "r"(c0), "r"(c1));
}
__device__ __forceinline__ void mmaf16_1688(unsigned* d, const unsigned* a,
                                            unsigned b0,
                                            unsigned c0, unsigned c1) {
    asm volatile(
        "mma.sync.aligned.m16n8k8.row.col.f16.f16.f16.f16 "
        "{%0,%1}, {%2,%3}, {%4}, {%5,%6};"
        : "=r"(d[0]), "=r"(d[1])
        : "r"(a[0]), "r"(a[1]), "r"(b0), "r"(c0), "r"(c1));
}
__device__ __forceinline__ unsigned movmt(unsigned a) {
    unsigned d;
    asm("movmatrix.sync.aligned.m8n8.trans.b16 %0, %1;" : "=r"(d) : "r"(a));
    return d;
}
__device__ __forceinline__ __half2 tanh2(__half2 x) {
    unsigned xi = *reinterpret_cast<unsigned*>(&x), yi;
    asm("tanh.approx.f16x2 %0, %1;" : "=r"(yi) : "r"(xi));
    return *reinterpret_cast<__half2*>(&yi);
}
__device__ __forceinline__ __half2 sig2(__half2 x) {
    const __half2 h05 = __float2half2_rn(0.5f);
    return __hfma2(tanh2(__hmul2(x, h05)), h05, h05);
}
__device__ __forceinline__ unsigned pack2(float lo, float hi) {
    __half2 h = __floats2half2_rn(lo, hi);
    return *reinterpret_cast<unsigned*>(&h);
}
__device__ __forceinline__ __half2 u2h(unsigned u) {
    return *reinterpret_cast<__half2*>(&u);
}

// ---------------------------------------------------------------------------
// Gate-split fused LSTM: 2-warp CTA owns 8 batch rows; warp p owns units
// [16p,16p+16), all 4 gates (12 MMA/warp/step, thread-local epilogue).
// R8: (1) own h-fragments stay in registers (only partner half via SMEM);
//     (2) x staged through SMEM in 32-step chunks (coalesced LDG.128 in,
//         conflict-free LDS out) -> L1 wavefront traffic cut ~5x.
// ---------------------------------------------------------------------------
__global__ void __launch_bounds__(64, 14) lstm_fused(
    const float* __restrict__ x,
    const int* __restrict__ mat_idx, const int* __restrict__ freq_idx,
    const float* __restrict__ W_ih, const float* __restrict__ W_hh,
    const float* __restrict__ b_ih, const float* __restrict__ b_hh,
    const float* __restrict__ mat_emb, const float* __restrict__ freq_emb,
    const float* __restrict__ fc_w, const float* __restrict__ fc_b,
    float* __restrict__ out, int T)
{
    __shared__ unsigned long long sx[2][2][32];   // [buf][warp][lane] h-frags
    __shared__ float sred[2][4][2];               // fc partials
    __shared__ float s_x[8][100];                 // x chunk: 8 rows x 32 steps x 3 (pad 100)

    const int tid  = threadIdx.x;
    const int wid  = tid >> 5, lane = tid & 31;
    const int q    = lane & 3;            // batch col-pair selector
    const int gid  = lane >> 2;           // row-in-tile

    const long long rowbase = (long long)blockIdx.x * 8;

    // ---- stationary A fragments: warp wid owns units [16*wid, 16*wid+16) ----
    auto wval = [&](int n, int k) -> float {
        if (k < 32)  return W_hh[n * 32 + k];
        if (k < 35)  return W_ih[n * 3 + (k - 32)];
        if (k == 35) return b_ih[n] + b_hh[n];
        return 0.f;
    };
    unsigned af[4][2][4];   // gate, k16-chunk, frag
    unsigned af2[4][2];     // k8 chunk (x + bias)
#pragma unroll
    for (int g = 0; g < 4; ++g) {
        int n0 = g * 32 + 16 * wid + gid, n1 = n0 + 8;
#pragma unroll
        for (int kc = 0; kc < 2; ++kc) {
            int k0 = 16 * kc + 2 * q;
            af[g][kc][0] = pack2(wval(n0, k0),     wval(n0, k0 + 1));
            af[g][kc][1] = pack2(wval(n1, k0),     wval(n1, k0 + 1));
            af[g][kc][2] = pack2(wval(n0, k0 + 8), wval(n0, k0 + 9));
            af[g][kc][3] = pack2(wval(n1, k0 + 8), wval(n1, k0 + 9));
        }
        int k2 = 32 + 2 * q;
        af2[g][0] = pack2(wval(n0, k2), wval(n0, k2 + 1));
        af2[g][1] = pack2(wval(n1, k2), wval(n1, k2 + 1));
    }

    // ---- x staging setup: thread (r=tid>>3, seg=tid&7) loads 12 floats ----
    const int xr = tid >> 3, xseg = tid & 7;
    const float* xsrc_base =
        x + (size_t)(rowbase + xr) * T * 3 + (size_t)xseg * 12;

    // ---- loop-carried state ----
    unsigned b00 = 0, b01 = 0, b10 = 0, b11 = 0;   // full h fragments (t=0: 0)
    __half2 cst[2];
    cst[0] = __float2half2_rn(0.f);
    cst[1] = __float2half2_rn(0.f);
    unsigned hs[2];
    hs[0] = hs[1] = 0u;

    float xp0 = 0.f, xp1 = 0.f, xp2 = 0.f;

    __syncthreads();   // s_x ready-to-write (trivial), sx zero-state not needed

    for (int t = 0; t < T; ++t) {
        if ((t & 31) == 0) {
            // stage chunk [t, t+32): 3x LDG.128 -> STS, coalesced
            const float4* src =
                reinterpret_cast<const float4*>(xsrc_base + (size_t)t * 3);
#pragma unroll
            for (int j = 0; j < 3; ++j) {
                float4 v = src[j];
                s_x[xr][xseg * 12 + j * 4 + 0] = v.x;
                s_x[xr][xseg * 12 + j * 4 + 1] = v.y;
                s_x[xr][xseg * 12 + j * 4 + 2] = v.z;
                s_x[xr][xseg * 12 + j * 4 + 3] = v.w;
            }
            __syncthreads();
            // read x for this step (tc = 0)
            if (q == 0)      { xp0 = s_x[gid][0]; xp1 = s_x[gid][1]; }
            else if (q == 1) { xp2 = s_x[gid][2]; }
        }

        unsigned b2;
        if (q == 0)      b2 = pack2(xp0, xp1);
        else if (q == 1) b2 = pack2(xp2, 1.f);
        else             b2 = 0u;

        // ---- 12 MMAs: x-projection (h-independent) first, then h chunks ----
        unsigned acc[4][2];
#pragma unroll
        for (int g = 0; g < 4; ++g)
            mmaf16_1688(acc[g], af2[g], b2, 0u, 0u);
#pragma unroll
        for (int g = 0; g < 4; ++g)
            mmaf16_16816(acc[g], af[g][0], b00, b01, acc[g][0], acc[g][1]);
#pragma unroll
        for (int g = 0; g < 4; ++g)
            mmaf16_16816(acc[g], af[g][1], b10, b11, acc[g][0], acc[g][1]);

        // ---- LSTM update: slot s -> unit 16*wid + 8*s + gid, batch {2q,2q+1}
#pragma unroll
        for (int s = 0; s < 2; ++s) {
            __half2 si = sig2(u2h(acc[0][s]));
            __half2 sf = sig2(u2h(acc[1][s]));
            __half2 tg = tanh2(u2h(acc[2][s]));
            __half2 so = sig2(u2h(acc[3][s]));
            __half2 cc = __hfma2(sf, cst[s], __hmul2(si, tg));
            cst[s] = cc;
            __half2 hv = __hmul2(so, tanh2(cc));
            hs[s] = *reinterpret_cast<unsigned*>(&hv);
        }

        // ---- own fragments in registers; partner half via SMEM ----
        unsigned f0 = movmt(hs[0]);        // k-rows 16*wid   .. +8
        unsigned f1 = movmt(hs[1]);        // k-rows 16*wid+8 .. +16
        const int buf = t & 1;
        sx[buf][wid][lane] =
            (unsigned long long)f0 | ((unsigned long long)f1 << 32);

        // prefetch x(t+1) from SMEM (same chunk only)
        if (((t + 1) & 31) != 0) {
            int tc1 = 3 * ((t + 1) & 31);
            if (q == 0)      { xp0 = s_x[gid][tc1]; xp1 = s_x[gid][tc1 + 1]; }
            else if (q == 1) { xp2 = s_x[gid][tc1 + 2]; }
        }

        __syncthreads();
        unsigned long long w = sx[buf][wid ^ 1][lane];
        if (wid == 0) {
            b00 = f0;          b01 = f1;
            b10 = (unsigned)w; b11 = (unsigned)(w >> 32);
        } else {
            b00 = (unsigned)w; b01 = (unsigned)(w >> 32);
            b10 = f0;          b11 = f1;
        }
    }

    // ---- fc head: partial over this warp's 16 units, then pair-reduce ----
    float p_lo = 0.f, p_hi = 0.f;          // batch rows rowbase+2q, +2q+1
#pragma unroll
    for (int s = 0; s < 2; ++s) {
        __half2 hv = u2h(hs[s]);
        float w = fc_w[16 * wid + 8 * s + gid];
        p_lo = fmaf(__low2float(hv),  w, p_lo);
        p_hi = fmaf(__high2float(hv), w, p_hi);
    }
#pragma unroll
    for (int off = 4; off < 32; off <<= 1) {
        p_lo += __shfl_xor_sync(0xFFFFFFFFu, p_lo, off);
        p_hi += __shfl_xor_sync(0xFFFFFFFFu, p_hi, off);
    }
    if (lane < 4) { sred[wid][q][0] = p_lo; sred[wid][q][1] = p_hi; }
    __syncthreads();
    if (tid < 4) {
        float base = fc_b[0];
#pragma unroll
        for (int k = 0; k < 2; ++k) {
            long long r = rowbase + 2 * tid + k;
            float s = sred[0][tid][k] + sred[1][tid][k] + base;
            int mi = mat_idx[r], fi = freq_idx[r];
#pragma unroll
            for (int e = 0; e < 4; ++e) s += mat_emb[mi * 4 + e] * fc_w[32 + e];
#pragma unroll
            for (int e = 0; e < 2; ++e) s += freq_emb[fi * 2 + e] * fc_w[36 + e];
            out[r] = s;
        }
    }
}

extern "C" void kernel_launch(void* const* d_in, const int* in_sizes, int n_in,
                              void* d_out, int out_size) {
    const float* x        = (const float*)d_in[0];
    const int*   mat_idx  = (const int*)  d_in[1];
    const int*   freq_idx = (const int*)  d_in[2];
    const float* W_ih     = (const float*)d_in[3];
    const float* W_hh     = (const float*)d_in[4];
    const float* b_ih     = (const float*)d_in[5];
    const float* b_hh     = (const float*)d_in[6];
    const float* mat_emb  = (const float*)d_in[7];
    const float* freq_emb = (const float*)d_in[8];
    const float* fc_w     = (const float*)d_in[9];
    const float* fc_b     = (const float*)d_in[10];

    int B = in_sizes[1];                  // mat_idx has B elements
    int T = in_sizes[0] / (B * 3);        // x has B*T*3 elements
    int grid = B / 8;                     // 8 rows per 2-warp CTA

    lstm_fused<<<grid, 64>>>(x, mat_idx, freq_idx, W_ih, W_hh, b_ih, b_hh,
                             mat_emb, freq_emb, fc_w, fc_b,
                             (float*)d_out, T);
}

// round 9
// speedup vs baseline: 1.2307x; 1.2307x over previous
#include <cuda_runtime.h>
#include <cuda_fp16.h>

// ---------------------------------------------------------------------------
// f16-accumulate MMA + movmatrix wrappers (sm_75+/sm_80, fine on compute_103)
// ---------------------------------------------------------------------------
__device__ __forceinline__ void mmaf16_16816(unsigned* d, const unsigned* a,
                                             unsigned b0, unsigned b1,
                                             unsigned c0, unsigned c1) {
    asm volatile(
        "mma.sync.aligned.m16n8k16.row.col.f16.f16.f16.f16 "
        "{%0,%1}, {%2,%3,%4,%5}, {%6,%7}, {%8,%9};"
        : "=r"(d[0]), "=r"(d[1])
        : "r"(a[0]), "r"(a[1]), "r"(a[2]), "r"(a[3]),
          "r"(b0), "r"(b1), "r"(c0), "r"(c1));
}
__device__ __forceinline__ void mmaf16_1688(unsigned* d, const unsigned* a,
                                            unsigned b0,
                                            unsigned c0, unsigned c1) {
    asm volatile(
        "mma.sync.aligned.m16n8k8.row.col.f16.f16.f16.f16 "
        "{%0,%1}, {%2,%3}, {%4}, {%5,%6};"
        : "=r"(d[0]), "=r"(d[1])
        : "r"(a[0]), "r"(a[1]), "r"(b0), "r"(c0), "r"(c1));
}
__device__ __forceinline__ unsigned movmt(unsigned a) {
    unsigned d;
    asm("movmatrix.sync.aligned.m8n8.trans.b16 %0, %1;" : "=r"(d) : "r"(a));
    return d;
}
__device__ __forceinline__ __half2 tanh2(__half2 x) {
    unsigned xi = *reinterpret_cast<unsigned*>(&x), yi;
    asm("tanh.approx.f16x2 %0, %1;" : "=r"(yi) : "r"(xi));
    return *reinterpret_cast<__half2*>(&yi);
}
// sigmoid with the 0.5 pre-folded into the weights: sig(2y) = 0.5*tanh(y)+0.5
__device__ __forceinline__ __half2 sig2h(__half2 y) {
    const __half2 h05 = __float2half2_rn(0.5f);
    return __hfma2(tanh2(y), h05, h05);
}
__device__ __forceinline__ unsigned pack2(float lo, float hi) {
    __half2 h = __floats2half2_rn(lo, hi);
    return *reinterpret_cast<unsigned*>(&h);
}
__device__ __forceinline__ __half2 u2h(unsigned u) {
    return *reinterpret_cast<__half2*>(&u);
}

// ---------------------------------------------------------------------------
// Gate-split fused LSTM: 2-warp CTA owns 8 batch rows; warp p owns units
// [16p,16p+16), all 4 gates (12 MMA/warp/step, thread-local epilogue).
// R9 diet: pre-packed half2 x staged per 32-step chunk (1 predicated LDS.32
// per step, zero cvt); sigmoid 0.5 folded into i/f/o weights; inner loop
// unrolled so buffer parity + LDS offsets are compile-time.
// ---------------------------------------------------------------------------
__global__ void __launch_bounds__(64, 14) lstm_fused(
    const float* __restrict__ x,
    const int* __restrict__ mat_idx, const int* __restrict__ freq_idx,
    const float* __restrict__ W_ih, const float* __restrict__ W_hh,
    const float* __restrict__ b_ih, const float* __restrict__ b_hh,
    const float* __restrict__ mat_emb, const float* __restrict__ freq_emb,
    const float* __restrict__ fc_w, const float* __restrict__ fc_b,
    float* __restrict__ out, int T)
{
    __shared__ unsigned long long sx[2][2][32];  // [buf][warp][lane] h-frags
    __shared__ float sred[2][4][2];              // fc partials
    __shared__ unsigned s_xh[32][16];            // [step][row*2+q] pre-packed x

    const int tid  = threadIdx.x;
    const int wid  = tid >> 5, lane = tid & 31;
    const int q    = lane & 3;            // batch col-pair selector
    const int gid  = lane >> 2;           // row-in-tile

    const long long rowbase = (long long)blockIdx.x * 8;

    // ---- stationary A fragments; 0.5 folded into sigmoid gates (0,1,3) ----
    auto wval = [&](int n, int k) -> float {
        float v;
        if (k < 32)       v = W_hh[n * 32 + k];
        else if (k < 35)  v = W_ih[n * 3 + (k - 32)];
        else if (k == 35) v = b_ih[n] + b_hh[n];
        else              v = 0.f;
        if ((n >> 5) != 2) v *= 0.5f;      // gates i,f,o scaled; g untouched
        return v;
    };
    unsigned af[4][2][4];   // gate, k16-chunk, frag
    unsigned af2[4][2];     // k8 chunk (x + bias)
#pragma unroll
    for (int g = 0; g < 4; ++g) {
        int n0 = g * 32 + 16 * wid + gid, n1 = n0 + 8;
#pragma unroll
        for (int kc = 0; kc < 2; ++kc) {
            int k0 = 16 * kc + 2 * q;
            af[g][kc][0] = pack2(wval(n0, k0),     wval(n0, k0 + 1));
            af[g][kc][1] = pack2(wval(n1, k0),     wval(n1, k0 + 1));
            af[g][kc][2] = pack2(wval(n0, k0 + 8), wval(n0, k0 + 9));
            af[g][kc][3] = pack2(wval(n1, k0 + 8), wval(n1, k0 + 9));
        }
        int k2 = 32 + 2 * q;
        af2[g][0] = pack2(wval(n0, k2), wval(n0, k2 + 1));
        af2[g][1] = pack2(wval(n1, k2), wval(n1, k2 + 1));
    }

    // ---- x staging setup: thread (xr=tid>>3, xseg=tid&7) handles 4 steps ----
    const int xr = tid >> 3, xseg = tid & 7;
    const float4* xsrc =
        reinterpret_cast<const float4*>(x + (size_t)(rowbase + xr) * T * 3)
        + xseg * 3;                        // 12 floats = steps 4*xseg..+4

    // ---- loop-carried state ----
    unsigned b00 = 0, b01 = 0, b10 = 0, b11 = 0;   // h fragments (t=0: 0)
    __half2 cst[2];
    cst[0] = __float2half2_rn(0.f);
    cst[1] = __float2half2_rn(0.f);
    unsigned hs[2];
    hs[0] = hs[1] = 0u;

    const bool xlane = (q < 2);
    const unsigned* xrow = &s_xh[0][gid * 2 + q];  // step stride = 16 words

    for (int tc = 0; tc < T; tc += 32) {
        // ---- stage chunk: 3x LDG.128, pre-pack to half2, 4x STS.64 ----
        {
            const float4* src = xsrc + (tc >> 5) * 24;   // 96 floats/chunk/row
            float4 v0 = src[0], v1 = src[1], v2 = src[2];
            float f[12] = {v0.x, v0.y, v0.z, v0.w, v1.x, v1.y, v1.z, v1.w,
                           v2.x, v2.y, v2.z, v2.w};
#pragma unroll
            for (int k = 0; k < 4; ++k) {
                unsigned lo = pack2(f[3 * k], f[3 * k + 1]);
                unsigned hi = pack2(f[3 * k + 2], 1.0f);
                s_xh[xseg * 4 + k][xr * 2 + 0] = lo;
                s_xh[xseg * 4 + k][xr * 2 + 1] = hi;
            }
        }
        __syncthreads();

#pragma unroll 4
        for (int tl = 0; tl < 32; ++tl) {
            const int buf = tl & 1;
            // x fragment: one predicated LDS.32, pre-packed
            unsigned b2 = 0u;
            if (xlane) b2 = xrow[tl * 16];

            // ---- 12 MMAs: x-projection (h-independent) first ----
            unsigned acc[4][2];
#pragma unroll
            for (int g = 0; g < 4; ++g)
                mmaf16_1688(acc[g], af2[g], b2, 0u, 0u);
#pragma unroll
            for (int g = 0; g < 4; ++g)
                mmaf16_16816(acc[g], af[g][0], b00, b01, acc[g][0], acc[g][1]);
#pragma unroll
            for (int g = 0; g < 4; ++g)
                mmaf16_16816(acc[g], af[g][1], b10, b11, acc[g][0], acc[g][1]);

            // ---- LSTM update (i,f,o pre-scaled by 0.5 in weights) ----
#pragma unroll
            for (int s = 0; s < 2; ++s) {
                __half2 si = sig2h(u2h(acc[0][s]));
                __half2 sf = sig2h(u2h(acc[1][s]));
                __half2 tg = tanh2(u2h(acc[2][s]));
                __half2 so = sig2h(u2h(acc[3][s]));
                __half2 cc = __hfma2(sf, cst[s], __hmul2(si, tg));
                cst[s] = cc;
                __half2 hv = __hmul2(so, tanh2(cc));
                hs[s] = *reinterpret_cast<unsigned*>(&hv);
            }

            // ---- own fragments in regs; partner half via SMEM ----
            unsigned f0 = movmt(hs[0]);    // k-rows 16*wid   .. +8
            unsigned f1 = movmt(hs[1]);    // k-rows 16*wid+8 .. +16
            sx[buf][wid][lane] =
                (unsigned long long)f0 | ((unsigned long long)f1 << 32);
            __syncthreads();
            unsigned long long w = sx[buf][wid ^ 1][lane];
            if (wid == 0) {
                b00 = f0;          b01 = f1;
                b10 = (unsigned)w; b11 = (unsigned)(w >> 32);
            } else {
                b00 = (unsigned)w; b01 = (unsigned)(w >> 32);
                b10 = f0;          b11 = f1;
            }
        }
    }

    // ---- fc head: partial over this warp's 16 units, then pair-reduce ----
    float p_lo = 0.f, p_hi = 0.f;          // batch rows rowbase+2q, +2q+1
#pragma unroll
    for (int s = 0; s < 2; ++s) {
        __half2 hv = u2h(hs[s]);
        float w = fc_w[16 * wid + 8 * s + gid];
        p_lo = fmaf(__low2float(hv),  w, p_lo);
        p_hi = fmaf(__high2float(hv), w, p_hi);
    }
#pragma unroll
    for (int off = 4; off < 32; off <<= 1) {
        p_lo += __shfl_xor_sync(0xFFFFFFFFu, p_lo, off);
        p_hi += __shfl_xor_sync(0xFFFFFFFFu, p_hi, off);
    }
    if (lane < 4) { sred[wid][q][0] = p_lo; sred[wid][q][1] = p_hi; }
    __syncthreads();
    if (tid < 4) {
        float base = fc_b[0];
#pragma unroll
        for (int k = 0; k < 2; ++k) {
            long long r = rowbase + 2 * tid + k;
            float s = sred[0][tid][k] + sred[1][tid][k] + base;
            int mi = mat_idx[r], fi = freq_idx[r];
#pragma unroll
            for (int e = 0; e < 4; ++e) s += mat_emb[mi * 4 + e] * fc_w[32 + e];
#pragma unroll
            for (int e = 0; e < 2; ++e) s += freq_emb[fi * 2 + e] * fc_w[36 + e];
            out[r] = s;
        }
    }
}

extern "C" void kernel_launch(void* const* d_in, const int* in_sizes, int n_in,
                              void* d_out, int out_size) {
    const float* x        = (const float*)d_in[0];
    const int*   mat_idx  = (const int*)  d_in[1];
    const int*   freq_idx = (const int*)  d_in[2];
    const float* W_ih     = (const float*)d_in[3];
    const float* W_hh     = (const float*)d_in[4];
    const float* b_ih     = (const float*)d_in[5];
    const float* b_hh     = (const float*)d_in[6];
    const float* mat_emb  = (const float*)d_in[7];
    const float* freq_emb = (const float*)d_in[8];
    const float* fc_w     = (const float*)d_in[9];
    const float* fc_b     = (const float*)d_in[10];

    int B = in_sizes[1];                  // mat_idx has B elements
    int T = in_sizes[0] / (B * 3);        // x has B*T*3 elements
    int grid = B / 8;                     // 8 rows per 2-warp CTA

    lstm_fused<<<grid, 64>>>(x, mat_idx, freq_idx, W_ih, W_hh, b_ih, b_hh,
                             mat_emb, freq_emb, fc_w, fc_b,
                             (float*)d_out, T);
}